// round 8
// baseline (speedup 1.0000x reference)
#include <cuda_runtime.h>
#include <cuda_bf16.h>
#include <math.h>
#include <stdint.h>

#define N_NODES 10000
#define N_EDGES 320000
#define MUL 32

__device__ __align__(16) float g_wkv [N_EDGES * 256];   // per-edge MLP outputs [wk(128)|wv(128)]
__device__ __align__(16) float g_qpre[N_NODES * 1024];  // per-node precomputed query side
__device__ __align__(16) float g_z   [N_NODES * 4];     // attention normalizer per head
__device__ __align__(16) float g_agg [N_NODES * 256];   // unnormalized aggregation
__device__ int g_cnt [N_NODES];
__device__ int g_off [N_NODES + 1];
__device__ int g_cur [N_NODES];
__device__ int g_eord[N_EDGES];

#define INV3F 0.57735026918962576f
#define INVFAN 0.015625f

// ---------------------------------------------------------------- f32x2 helpers
__device__ __forceinline__ uint64_t pack2(float lo, float hi) {
    uint64_t r; asm("mov.b64 %0, {%1, %2};" : "=l"(r) : "f"(lo), "f"(hi)); return r;
}
__device__ __forceinline__ void unpack2(uint64_t v, float& lo, float& hi) {
    asm("mov.b64 {%0, %1}, %2;" : "=f"(lo), "=f"(hi) : "l"(v));
}
__device__ __forceinline__ void fmaX2(uint64_t& c, uint64_t a, uint64_t b) {
    asm("fma.rn.f32x2 %0, %1, %2, %0;" : "+l"(c) : "l"(a), "l"(b));
}

// ---------------------------------------------------------------- tiny init
__global__ void ek_zero0() {
    int i = blockIdx.x * blockDim.x + threadIdx.x;
    if (i < N_NODES) g_cnt[i] = 0;
}
// ---------------------------------------------------------------- histogram
__global__ void ek_hist(const int* __restrict__ edst) {
    int e = blockIdx.x * blockDim.x + threadIdx.x;
    if (e < N_EDGES) atomicAdd(&g_cnt[edst[e]], 1);
}
// ---------------------------------------------------------------- scan (1 block)
__global__ void __launch_bounds__(256) ek_scan() {
    __shared__ int s_part[256];
    int t = threadIdx.x;
    int base = t * 40;
    int s = 0;
    for (int i = 0; i < 40; i++) { int idx = base + i; if (idx < N_NODES) s += g_cnt[idx]; }
    s_part[t] = s;
    __syncthreads();
    for (int off = 1; off < 256; off <<= 1) {
        int v = (t >= off) ? s_part[t - off] : 0;
        __syncthreads();
        s_part[t] += v;
        __syncthreads();
    }
    int run = s_part[t] - s;
    for (int i = 0; i < 40; i++) {
        int idx = base + i;
        if (idx < N_NODES) { g_off[idx] = run; g_cur[idx] = run; run += g_cnt[idx]; }
    }
    if (t == 0) g_off[N_NODES] = N_EDGES;
}
// ---------------------------------------------------------------- scatter
__global__ void ek_scatter(const int* __restrict__ edst) {
    int e = blockIdx.x * blockDim.x + threadIdx.x;
    if (e < N_EDGES) {
        int pos = atomicAdd(&g_cur[edst[e]], 1);
        g_eord[pos] = e;
    }
}

// ---------------------------------------------------------------- f32x2 dual MLP
// 64 edges/block (32 edge-pairs), 256 threads. Layer1 scalar 8->128 hidden
// (hk|hv) + gelu into smem. Layer2: C[64e][256n] = H K-dot with per-thread
// 4-pair x 8-output tiles of fma.rn.f32x2 (packed fp32, 2x FFMA rate).
// smem floats: s_h[128][64] @0 (32KB) | s_w2[64][256] @8192 (64KB)
//              | s_w1[2][512] @24576 | s_b1[128] @25600  => 102,912 B
#define MLP_SMEM 102912
__global__ void __launch_bounds__(256, 2) ek_mlp_kernel(const float* __restrict__ xattr,
    const float* __restrict__ wk1, const float* __restrict__ bk1, const float* __restrict__ wk2,
    const float* __restrict__ wv1, const float* __restrict__ bv1, const float* __restrict__ wv2) {
    extern __shared__ float sm[];
    float* s_h  = sm;
    float* s_w2 = sm + 8192;
    float* s_w1 = sm + 24576;
    float* s_b1 = sm + 25600;
    int t = threadIdx.x;
    int e0 = blockIdx.x * 64;

    for (int i = t; i < 8192; i += 256) {
        int k = i >> 7, n = i & 127;
        s_w2[k * 256 + n]       = wk2[i];
        s_w2[k * 256 + 128 + n] = wv2[i];
    }
    for (int i = t; i < 1024; i += 256) s_w1[i] = (i < 512) ? wk1[i] : wv1[i - 512];
    if (t < 128) s_b1[t] = (t < 64) ? bk1[t] : bv1[t - 64];
    __syncthreads();

    // layer1: thread -> (edge e, group grp); grp: part=grp>>1, cbase=(grp&1)*32
    {
        int e = t & 63, grp = t >> 6;
        int part = grp >> 1, cb = (grp & 1) * 32;
        const float4* xp = (const float4*)(xattr + (size_t)(e0 + e) * 8);
        float4 xa = xp[0], xb = xp[1];
        const float* w1 = s_w1 + part * 512;
        const float* bb = s_b1 + part * 64;
        float* hout = s_h + (part * 64 + cb) * 64 + e;
#pragma unroll 8
        for (int cc = 0; cc < 32; cc++) {
            int c = cb + cc;
            float acc = xa.x * w1[c]       + xa.y * w1[64 + c]  + xa.z * w1[128 + c] + xa.w * w1[192 + c]
                      + xb.x * w1[256 + c] + xb.y * w1[320 + c] + xb.z * w1[384 + c] + xb.w * w1[448 + c];
            acc = acc * 0.35355339059327373f + bb[c];
            float u2 = 0.7978845608028654f * (acc + 0.044715f * acc * acc * acc);
            float th;
            asm("tanh.approx.f32 %0, %1;" : "=f"(th) : "f"(u2));
            hout[cc * 64] = 0.5f * acc * (1.f + th);
        }
    }
    __syncthreads();

    // layer2: pairtile pt = t&7 (4 pairs = 8 edges' floats), outtile ot = t>>3 (8 outs)
    int pt = t & 7, ot = t >> 3;
    const float* hp = s_h + ((ot >= 16) ? 64 * 64 : 0) + pt * 8;
    const float* wp = s_w2 + ot * 8;
    uint64_t acc[4][8];
#pragma unroll
    for (int p = 0; p < 4; p++)
#pragma unroll
        for (int o = 0; o < 8; o++) acc[p][o] = 0ull;

#pragma unroll 8
    for (int k = 0; k < 64; k++) {
        float4 h0 = *(const float4*)(hp + k * 64);
        float4 h1 = *(const float4*)(hp + k * 64 + 4);
        float4 w0 = *(const float4*)(wp + k * 256);
        float4 w1v = *(const float4*)(wp + k * 256 + 4);
        uint64_t hx[4] = { pack2(h0.x, h0.y), pack2(h0.z, h0.w),
                           pack2(h1.x, h1.y), pack2(h1.z, h1.w) };
        uint64_t wd[8] = { pack2(w0.x, w0.x), pack2(w0.y, w0.y), pack2(w0.z, w0.z), pack2(w0.w, w0.w),
                           pack2(w1v.x, w1v.x), pack2(w1v.y, w1v.y), pack2(w1v.z, w1v.z), pack2(w1v.w, w1v.w) };
#pragma unroll
        for (int p = 0; p < 4; p++)
#pragma unroll
            for (int o = 0; o < 8; o++) fmaX2(acc[p][o], hx[p], wd[o]);
    }

    const float inv64 = 0.125f;
    int n0 = ot * 8;
#pragma unroll
    for (int p = 0; p < 4; p++) {
        int elo = e0 + pt * 8 + p * 2;
        float lo[8], hi[8];
#pragma unroll
        for (int o = 0; o < 8; o++) { unpack2(acc[p][o], lo[o], hi[o]); lo[o] *= inv64; hi[o] *= inv64; }
        float* d0 = g_wkv + (size_t)elo * 256 + n0;
        float* d1 = d0 + 256;
        __stcs((float4*)d0,       make_float4(lo[0], lo[1], lo[2], lo[3]));
        __stcs((float4*)(d0 + 4), make_float4(lo[4], lo[5], lo[6], lo[7]));
        __stcs((float4*)d1,       make_float4(hi[0], hi[1], hi[2], hi[3]));
        __stcs((float4*)(d1 + 4), make_float4(hi[4], hi[5], hi[6], hi[7]));
    }
}

// ---------------------------------------------------------------- Qpre precompute
__global__ void __launch_bounds__(256) ek_qpre_kernel(const float* __restrict__ nodef,
                                                      const float* __restrict__ wdot) {
    extern __shared__ float qsm[];
    float* s_w = qsm;            // 16384 floats
    float* s_x = qsm + 16384;    // 128 floats
    int t = threadIdx.x;
    for (int i = t; i < 16384; i += 256) s_w[i] = wdot[i];
    for (int nn = 0; nn < 10; nn++) {
        int n = blockIdx.x * 10 + nn;
        __syncthreads();
        if (t < 32) *(float4*)&s_x[t * 4] = *(const float4*)(nodef + (size_t)n * 128 + t * 4);
        __syncthreads();
#pragma unroll
        for (int rep = 0; rep < 4; rep++) {
            int o = t + rep * 256;
            int h = o >> 8, i = o & 255;
            float acc = 0.f;
            if (i < 64) {
                int p = (i < 32) ? 0 : 1;
                int v = i & 31;
                const float* W = s_w + (p * 4 + h) * 1024 + v;
#pragma unroll
                for (int u = 0; u < 32; u++) acc += s_x[u] * W[u * 32];
                acc *= INVFAN;
            } else {
                int p  = (i < 160) ? 2 : 3;
                int tt = (i < 160) ? (i - 64) : (i - 160);
                int d = tt >> 5, v = tt & 31;
                const float* W = s_w + (p * 4 + h) * 1024 + v;
#pragma unroll
                for (int u = 0; u < 32; u++) acc += s_x[32 + 3 * u + d] * W[u * 32];
                acc *= INVFAN * INV3F;
            }
            g_qpre[(size_t)n * 1024 + o] = acc;
        }
    }
}

// ---------------------------------------------------------------- per-dst edge kernel
__device__ __forceinline__ float feat_base(int i, const float* row,
                                           float ys, float yv0, float yv1, float yv2,
                                           int& widx) {
    if (i < 32) { widx = i; return row[i] * ys; }
    if (i < 64) {
        int u = i - 32; widx = i;
        return (row[32 + 3 * u] * yv0 + row[33 + 3 * u] * yv1 + row[34 + 3 * u] * yv2) * INV3F;
    }
    if (i < 160) {
        int tt = i - 64; int d = tt >> 5, u = tt & 31; widx = 64 + u;
        float yd = (d == 0) ? yv0 : ((d == 1) ? yv1 : yv2);
        return row[u] * yd;
    }
    {
        int tt = i - 160; int d = tt >> 5, u = tt & 31; widx = 96 + u;
        return row[32 + 3 * u + d] * ys;
    }
}
__device__ __forceinline__ int feat_head(int i) {
    if (i < 64) return (i & 31) >> 3;
    int tt = (i < 160) ? (i - 64) : (i - 160);
    return (tt & 31) >> 3;
}

#define DEG_CAP 160
__global__ void __launch_bounds__(256) ek_edge_dst(
    const int* __restrict__ esrc,
    const float* __restrict__ eattr, const float* __restrict__ ecut,
    const float* __restrict__ nodef) {
    __shared__ int   s_ids [8][DEG_CAP];
    __shared__ int   s_ids2[8][DEG_CAP];
    __shared__ float s_row [8][132];
    __shared__ float s_wkv [8][264];
    int warp = threadIdx.x >> 5, lane = threadIdx.x & 31;
    int dst = blockIdx.x * 8 + warp;
    if (dst >= N_NODES) return;

    int start = g_off[dst];
    int cnt   = g_off[dst + 1] - start;

    const float4* q = (const float4*)(g_qpre + (size_t)dst * 1024);
    float4 qa[4], qb[4];
#pragma unroll
    for (int h = 0; h < 4; h++) { qa[h] = q[h * 64 + lane]; qb[h] = q[h * 64 + 32 + lane]; }

    int iA = 4 * lane, iB = 128 + 4 * lane;
    float accA[4] = {0.f, 0.f, 0.f, 0.f}, accB[4] = {0.f, 0.f, 0.f, 0.f};
    float zz[4] = {0.f, 0.f, 0.f, 0.f};

    if (cnt > 0) {
        bool sorted = (cnt <= DEG_CAP);
        if (sorted) {
            for (int p = lane; p < cnt; p += 32) s_ids[warp][p] = g_eord[start + p];
            __syncwarp();
            for (int p = lane; p < cnt; p += 32) {
                int myid = s_ids[warp][p], r = 0;
                for (int j = 0; j < cnt; j++) r += (s_ids[warp][j] < myid);
                s_ids2[warp][r] = myid;
            }
            __syncwarp();
        }
        int eid = sorted ? s_ids2[warp][0] : g_eord[start];
        int s   = esrc[eid];
        for (int k2 = 0; k2 < cnt; k2++) {
            float4 ea = *(const float4*)(eattr + (size_t)eid * 4);
            float ys = ea.x, yv0 = ea.y, yv1 = ea.z, yv2 = ea.w;
            float cw = ecut[eid];
            *(float4*)&s_row[warp][lane * 4] = *(const float4*)(nodef + (size_t)s * 128 + lane * 4);
            const float4* wv4 = (const float4*)(g_wkv + (size_t)eid * 256);
            *(float4*)&s_wkv[warp][lane * 4]       = __ldcs(wv4 + lane);
            *(float4*)&s_wkv[warp][128 + lane * 4] = __ldcs(wv4 + 32 + lane);
            int eid_n = 0, s_n = 0;
            if (k2 + 1 < cnt) {
                eid_n = sorted ? s_ids2[warp][k2 + 1] : g_eord[start + k2 + 1];
                s_n = esrc[eid_n];
            }
            __syncwarp();

            const float* row = s_row[warp];
            const float* wk  = s_wkv[warp];
            float bA[4], bB[4];
            int   xA[4], xB[4];
#pragma unroll
            for (int j = 0; j < 4; j++) {
                bA[j] = feat_base(iA + j, row, ys, yv0, yv1, yv2, xA[j]);
                bB[j] = feat_base(iB + j, row, ys, yv0, yv1, yv2, xB[j]);
            }
            float kA[4], kB[4];
#pragma unroll
            for (int j = 0; j < 4; j++) { kA[j] = wk[xA[j]] * bA[j]; kB[j] = wk[xB[j]] * bB[j]; }

            float dh[4];
#pragma unroll
            for (int h = 0; h < 4; h++) {
                dh[h] = qa[h].x * kA[0] + qa[h].y * kA[1] + qa[h].z * kA[2] + qa[h].w * kA[3]
                      + qb[h].x * kB[0] + qb[h].y * kB[1] + qb[h].z * kB[2] + qb[h].w * kB[3];
            }
#pragma unroll
            for (int off = 16; off; off >>= 1) {
#pragma unroll
                for (int h = 0; h < 4; h++) dh[h] += __shfl_xor_sync(0xffffffffu, dh[h], off);
            }
            float sa[4];
#pragma unroll
            for (int h = 0; h < 4; h++) {
                float ew = cw * expf(dh[h]);
                zz[h] += ew;
                sa[h] = sqrtf(ew);
            }
            const float* wv = wk + 128;
#pragma unroll
            for (int j = 0; j < 4; j++) {
                accA[j] += wv[xA[j]] * bA[j] * sa[feat_head(iA + j)];
                accB[j] += wv[xB[j]] * bB[j] * sa[feat_head(iB + j)];
            }
            __syncwarp();
            eid = eid_n; s = s_n;
        }
    }
    if (lane == 0) *(float4*)(g_z + (size_t)dst * 4) = make_float4(zz[0], zz[1], zz[2], zz[3]);
    *(float4*)(g_agg + (size_t)dst * 256 + iA) = make_float4(accA[0], accA[1], accA[2], accA[3]);
    *(float4*)(g_agg + (size_t)dst * 256 + iB) = make_float4(accB[0], accB[1], accB[2], accB[3]);
}

// ---------------------------------------------------------------- node epilogue
__global__ void __launch_bounds__(128) ek_out_kernel(const float* __restrict__ wls,
                                                     const float* __restrict__ wlv,
                                                     float* __restrict__ out) {
    __shared__ float s_ws[2048];
    __shared__ float s_wv[2048];
    __shared__ float s_s[64];
    __shared__ float s_v[192];
    __shared__ float s_sc[4];
    int t = threadIdx.x;
    for (int i = t; i < 2048; i += 128) { s_ws[i] = wls[i]; s_wv[i] = wlv[i]; }
    const float inv_l = 0.125f;

    for (int nn = 0; nn < 10; nn++) {
        int n = blockIdx.x * 10 + nn;
        __syncthreads();
        if (t < 4) {
            float zz = g_z[(size_t)n * 4 + t];
            s_sc[t] = (zz == 0.f) ? 1.f : (1.0f / sqrtf(zz));
        }
        __syncthreads();
        for (int i = t; i < 256; i += 128) {
            float val = g_agg[(size_t)n * 256 + i];
            if (i < 64) {
                s_s[i] = val * s_sc[(i & 31) >> 3];
            } else {
                int f = i - 64;
                int blk = (f < 96) ? 0 : 1;
                int r = f - blk * 96;
                int d = r >> 5, uu = r & 31;
                s_v[d * 64 + blk * 32 + uu] = val * s_sc[uu >> 3];
            }
        }
        __syncthreads();
        if (t < 32) {
            int w = t;
            float acc = 0.f;
#pragma unroll
            for (int u = 0; u < 64; u++) acc += s_s[u] * s_ws[u * 32 + w];
            out[(size_t)n * 128 + w] = acc * inv_l;
        } else {
            int o = t - 32;
            int d = o >> 5, w = o & 31;
            float acc = 0.f;
#pragma unroll
            for (int u = 0; u < 64; u++) acc += s_v[d * 64 + u] * s_wv[u * 32 + w];
            out[(size_t)n * 128 + 32 + w * 3 + d] = acc * inv_l;
        }
    }
}

// ---------------------------------------------------------------- launch
extern "C" void kernel_launch(void* const* d_in, const int* in_sizes, int n_in,
                              void* d_out, int out_size) {
    const int*   esrc  = (const int*)d_in[0];
    const int*   edst  = (const int*)d_in[1];
    const float* xattr = (const float*)d_in[2];
    const float* eattr = (const float*)d_in[3];
    const float* ecut  = (const float*)d_in[4];
    const float* nodef = (const float*)d_in[5];
    const float* wk1   = (const float*)d_in[6];
    const float* bk1   = (const float*)d_in[7];
    const float* wk2   = (const float*)d_in[8];
    const float* wv1   = (const float*)d_in[9];
    const float* bv1   = (const float*)d_in[10];
    const float* wv2   = (const float*)d_in[11];
    const float* wdot  = (const float*)d_in[12];
    const float* wls   = (const float*)d_in[13];
    const float* wlv   = (const float*)d_in[14];
    float* out = (float*)d_out;

    const int qpre_smem = 16512 * 4;   // 66,048 B
    cudaFuncSetAttribute(ek_qpre_kernel, cudaFuncAttributeMaxDynamicSharedMemorySize, qpre_smem);
    cudaFuncSetAttribute(ek_mlp_kernel,  cudaFuncAttributeMaxDynamicSharedMemorySize, MLP_SMEM);

    // Launch index 3 (ek_mlp_kernel) is the one ncu captures — keep it there.
    ek_zero0<<<(N_NODES + 255) / 256, 256>>>();
    ek_hist<<<N_EDGES / 256, 256>>>(edst);
    ek_scan<<<1, 256>>>();
    ek_mlp_kernel<<<N_EDGES / 64, 256, MLP_SMEM>>>(xattr, wk1, bk1, wk2, wv1, bv1, wv2);
    ek_scatter<<<N_EDGES / 256, 256>>>(edst);
    ek_qpre_kernel<<<N_NODES / 10, 256, qpre_smem>>>(nodef, wdot);
    ek_edge_dst<<<(N_NODES + 7) / 8, 256>>>(esrc, eattr, ecut, nodef);
    ek_out_kernel<<<N_NODES / 10, 128>>>(wls, wlv, out);
}